// round 4
// baseline (speedup 1.0000x reference)
#include <cuda_runtime.h>
#include <cuda_bf16.h>

// ---------------------------------------------------------------------------
// QuantumLayerVQC — 3-qubit, 3-layer VQC, B ~ 1M samples.
//
// Math:  z(b) = psi(b)^T ReM psi(b),  psi = kron over q of (cos x_q/2, sin x_q/2)
// where ReM = Re(U^dag Z0 U) depends only on q_weights.  Per qubit the
// quadratic monomials {c^2, s^2, cs} map (double angle) to {1, cos x, sin x},
// so z is trilinear in m_q = (1, cos x_q, sin x_q) with 27 coefficients D.
//
// Kernel 1 (1 block): evolve 8 basis columns -> U, form ReM, contract -> D[27].
// Kernel 2 (streaming): per sample float4 load, 3x sincos, 26 FMA, store.
// ---------------------------------------------------------------------------

__device__ float g_D[27];

__device__ __forceinline__ void swp(float& a, float& b) { float t = a; a = b; b = t; }

__global__ void vqc_setup_kernel(const float* __restrict__ w) {
    // w: (3 layers, 3 qubits, 2) = 18 floats: [l][q][0]=RY angle, [l][q][1]=RZ angle
    __shared__ float Ur[8][8];  // [amplitude k][column j]
    __shared__ float Ui[8][8];
    __shared__ float Ms[8][8];  // ReM

    int t = threadIdx.x;

    if (t < 8) {
        // Evolve basis column j = t through the parameterized circuit.
        float ur[8], ui[8];
        #pragma unroll
        for (int k = 0; k < 8; k++) { ur[k] = (k == t) ? 1.f : 0.f; ui[k] = 0.f; }

        for (int l = 0; l < 3; l++) {
            for (int q = 0; q < 3; q++) {
                float thy = w[(l * 3 + q) * 2 + 0];
                float thz = w[(l * 3 + q) * 2 + 1];
                int s = 4 >> q;  // bit stride: q0->4, q1->2, q2->1

                // RY(thy) on qubit q: real rotation on (i, i+s) pairs
                float cy, sy; sincosf(0.5f * thy, &sy, &cy);
                #pragma unroll
                for (int i = 0; i < 8; i++) {
                    if (i & s) continue;
                    float ar = ur[i],     ai = ui[i];
                    float br = ur[i + s], bi = ui[i + s];
                    ur[i]     = cy * ar - sy * br;  ui[i]     = cy * ai - sy * bi;
                    ur[i + s] = sy * ar + cy * br;  ui[i + s] = sy * ai + cy * bi;
                }

                // RZ(thz): bit=0 -> e^{-i thz/2}, bit=1 -> e^{+i thz/2}
                float cz, sz; sincosf(0.5f * thz, &sz, &cz);
                #pragma unroll
                for (int i = 0; i < 8; i++) {
                    float ph = (i & s) ? sz : -sz;  // imaginary part of phase
                    float ar = ur[i], ai = ui[i];
                    ur[i] = cz * ar - ph * ai;
                    ui[i] = cz * ai + ph * ar;
                }
            }
            // CNOT01 (control bit2, target bit1): swap 4<->6, 5<->7
            swp(ur[4], ur[6]); swp(ui[4], ui[6]);
            swp(ur[5], ur[7]); swp(ui[5], ui[7]);
            // CNOT12 (control bit1, target bit0): swap 2<->3, 6<->7
            swp(ur[2], ur[3]); swp(ui[2], ui[3]);
            swp(ur[6], ur[7]); swp(ui[6], ui[7]);
        }
        #pragma unroll
        for (int k = 0; k < 8; k++) { Ur[k][t] = ur[k]; Ui[k][t] = ui[k]; }
    }
    __syncthreads();

    if (t < 64) {
        // ReM[i][j] = sum_k sign(k) * Re(conj(U[k][i]) * U[k][j]),
        // sign = +1 for k<4 (q0=0), -1 otherwise.
        int i = t >> 3, j = t & 7;
        float m = 0.f;
        #pragma unroll
        for (int k = 0; k < 8; k++) {
            float sgn = (k < 4) ? 1.f : -1.f;
            m += sgn * (Ur[k][i] * Ur[k][j] + Ui[k][i] * Ui[k][j]);
        }
        Ms[i][j] = m;
    }
    __syncthreads();

    if (t < 27) {
        // Per-qubit pair-(b,b') -> basis (1, cos, sin) transform:
        //   c^2 = 1/2 + 1/2 cos,  c*s = 1/2 sin,  s^2 = 1/2 - 1/2 cos
        const float T[4][3] = {
            {0.5f,  0.5f, 0.0f},   // (0,0)
            {0.0f,  0.0f, 0.5f},   // (0,1)
            {0.0f,  0.0f, 0.5f},   // (1,0)
            {0.5f, -0.5f, 0.0f},   // (1,1)
        };
        int p0 = t / 9, p1 = (t / 3) % 3, p2 = t % 3;
        float d = 0.f;
        #pragma unroll
        for (int i = 0; i < 8; i++) {
            #pragma unroll
            for (int j = 0; j < 8; j++) {
                int pr0 = (((i >> 2) & 1) << 1) | ((j >> 2) & 1);
                int pr1 = (((i >> 1) & 1) << 1) | ((j >> 1) & 1);
                int pr2 = ((i & 1) << 1) | (j & 1);
                d += Ms[i][j] * T[pr0][p0] * T[pr1][p1] * T[pr2][p2];
            }
        }
        g_D[t] = d;
    }
}

static constexpr int TPB = 256;
static constexpr int ILP = 4;

__global__ void __launch_bounds__(TPB) vqc_main_kernel(
    const float* __restrict__ in,  // (B, 8)
    float* __restrict__ out,       // (B,)
    int B
) {
    // Warp-uniform coefficients: loaded once, amortized over ILP samples.
    float D[27];
    #pragma unroll
    for (int i = 0; i < 27; i++) D[i] = g_D[i];

    int base = blockIdx.x * (TPB * ILP) + threadIdx.x;
    #pragma unroll
    for (int it = 0; it < ILP; it++) {
        int idx = base + it * TPB;
        if (idx < B) {
            // Row is 32 bytes; only x0..x2 used. 16B aligned vector load.
            float4 x = __ldg(reinterpret_cast<const float4*>(in) + idx * 2);
            float s0, c0, s1, c1, s2, c2;
            __sincosf(x.x, &s0, &c0);
            __sincosf(x.y, &s1, &c1);
            __sincosf(x.z, &s2, &c2);

            float z = 0.f;
            #pragma unroll
            for (int p0 = 0; p0 < 3; p0++) {
                float u = 0.f;
                #pragma unroll
                for (int p1 = 0; p1 < 3; p1++) {
                    const float* d = &D[p0 * 9 + p1 * 3];
                    float v = d[0] + d[1] * c2 + d[2] * s2;
                    float m1 = (p1 == 0) ? 1.f : ((p1 == 1) ? c1 : s1);
                    u = fmaf(v, m1, u);
                }
                float m0 = (p0 == 0) ? 1.f : ((p0 == 1) ? c0 : s0);
                z = fmaf(u, m0, z);
            }
            out[idx] = z;
        }
    }
}

extern "C" void kernel_launch(void* const* d_in, const int* in_sizes, int n_in,
                              void* d_out, int out_size) {
    // inputs: (B,8) float32; q_weights: (3,3,2)=18 float32.  Be robust to order.
    const float* in = (const float*)d_in[0];
    const float* w  = (const float*)d_in[1];
    int sz0 = in_sizes[0], sz1 = in_sizes[1];
    if (sz0 == 18 && sz1 != 18) {
        const float* tmp = in; in = w; w = tmp;
        int ts = sz0; sz0 = sz1; sz1 = ts;
    }
    int B = sz0 / 8;
    float* out = (float*)d_out;

    vqc_setup_kernel<<<1, 64>>>(w);
    int grid = (B + TPB * ILP - 1) / (TPB * ILP);
    vqc_main_kernel<<<grid, TPB>>>(in, out, B);
}

// round 5
// speedup vs baseline: 1.0175x; 1.0175x over previous
#include <cuda_runtime.h>
#include <cuda_bf16.h>

// ---------------------------------------------------------------------------
// QuantumLayerVQC — 3-qubit, 3-layer VQC, B ~ 1M samples.
//
// Math:  z(b) = psi(b)^T ReM psi(b),  psi = kron over q of (cos x_q/2, sin x_q/2)
// where ReM = Re(U^dag Z0 U) depends only on q_weights.  Per qubit the
// quadratic monomials {c^2, s^2, cs} map (double angle) to {1, cos x, sin x},
// so z is trilinear in m_q = (1, cos x_q, sin x_q) with 27 coefficients D.
//
// Kernel 1 (1 block): evolve 8 basis columns -> U, form ReM, contract -> D[27].
// Kernel 2 (streaming): per sample float4 load, 3x sincos, 26 FMA, store.
// ---------------------------------------------------------------------------

__device__ float g_D[27];

__device__ __forceinline__ void swp(float& a, float& b) { float t = a; a = b; b = t; }

__global__ void vqc_setup_kernel(const float* __restrict__ w) {
    // w: (3 layers, 3 qubits, 2) = 18 floats: [l][q][0]=RY angle, [l][q][1]=RZ angle
    __shared__ float Ur[8][8];  // [amplitude k][column j]
    __shared__ float Ui[8][8];
    __shared__ float Ms[8][8];  // ReM

    int t = threadIdx.x;

    if (t < 8) {
        // Evolve basis column j = t through the parameterized circuit.
        float ur[8], ui[8];
        #pragma unroll
        for (int k = 0; k < 8; k++) { ur[k] = (k == t) ? 1.f : 0.f; ui[k] = 0.f; }

        for (int l = 0; l < 3; l++) {
            for (int q = 0; q < 3; q++) {
                float thy = w[(l * 3 + q) * 2 + 0];
                float thz = w[(l * 3 + q) * 2 + 1];
                int s = 4 >> q;  // bit stride: q0->4, q1->2, q2->1

                // RY(thy) on qubit q: real rotation on (i, i+s) pairs
                float cy, sy; sincosf(0.5f * thy, &sy, &cy);
                #pragma unroll
                for (int i = 0; i < 8; i++) {
                    if (i & s) continue;
                    float ar = ur[i],     ai = ui[i];
                    float br = ur[i + s], bi = ui[i + s];
                    ur[i]     = cy * ar - sy * br;  ui[i]     = cy * ai - sy * bi;
                    ur[i + s] = sy * ar + cy * br;  ui[i + s] = sy * ai + cy * bi;
                }

                // RZ(thz): bit=0 -> e^{-i thz/2}, bit=1 -> e^{+i thz/2}
                float cz, sz; sincosf(0.5f * thz, &sz, &cz);
                #pragma unroll
                for (int i = 0; i < 8; i++) {
                    float ph = (i & s) ? sz : -sz;  // imaginary part of phase
                    float ar = ur[i], ai = ui[i];
                    ur[i] = cz * ar - ph * ai;
                    ui[i] = cz * ai + ph * ar;
                }
            }
            // CNOT01 (control bit2, target bit1): swap 4<->6, 5<->7
            swp(ur[4], ur[6]); swp(ui[4], ui[6]);
            swp(ur[5], ur[7]); swp(ui[5], ui[7]);
            // CNOT12 (control bit1, target bit0): swap 2<->3, 6<->7
            swp(ur[2], ur[3]); swp(ui[2], ui[3]);
            swp(ur[6], ur[7]); swp(ui[6], ui[7]);
        }
        #pragma unroll
        for (int k = 0; k < 8; k++) { Ur[k][t] = ur[k]; Ui[k][t] = ui[k]; }
    }
    __syncthreads();

    if (t < 64) {
        // ReM[i][j] = sum_k sign(k) * Re(conj(U[k][i]) * U[k][j]),
        // sign = +1 for k<4 (q0=0), -1 otherwise.
        int i = t >> 3, j = t & 7;
        float m = 0.f;
        #pragma unroll
        for (int k = 0; k < 8; k++) {
            float sgn = (k < 4) ? 1.f : -1.f;
            m += sgn * (Ur[k][i] * Ur[k][j] + Ui[k][i] * Ui[k][j]);
        }
        Ms[i][j] = m;
    }
    __syncthreads();

    if (t < 27) {
        // Per-qubit pair-(b,b') -> basis (1, cos, sin) transform:
        //   c^2 = 1/2 + 1/2 cos,  c*s = 1/2 sin,  s^2 = 1/2 - 1/2 cos
        const float T[4][3] = {
            {0.5f,  0.5f, 0.0f},   // (0,0)
            {0.0f,  0.0f, 0.5f},   // (0,1)
            {0.0f,  0.0f, 0.5f},   // (1,0)
            {0.5f, -0.5f, 0.0f},   // (1,1)
        };
        int p0 = t / 9, p1 = (t / 3) % 3, p2 = t % 3;
        float d = 0.f;
        #pragma unroll
        for (int i = 0; i < 8; i++) {
            #pragma unroll
            for (int j = 0; j < 8; j++) {
                int pr0 = (((i >> 2) & 1) << 1) | ((j >> 2) & 1);
                int pr1 = (((i >> 1) & 1) << 1) | ((j >> 1) & 1);
                int pr2 = ((i & 1) << 1) | (j & 1);
                d += Ms[i][j] * T[pr0][p0] * T[pr1][p1] * T[pr2][p2];
            }
        }
        g_D[t] = d;
    }
}

static constexpr int TPB = 256;
static constexpr int ILP = 4;

__global__ void __launch_bounds__(TPB) vqc_main_kernel(
    const float* __restrict__ in,  // (B, 8)
    float* __restrict__ out,       // (B,)
    int B
) {
    // Warp-uniform coefficients: loaded once, amortized over ILP samples.
    float D[27];
    #pragma unroll
    for (int i = 0; i < 27; i++) D[i] = g_D[i];

    int base = blockIdx.x * (TPB * ILP) + threadIdx.x;
    #pragma unroll
    for (int it = 0; it < ILP; it++) {
        int idx = base + it * TPB;
        if (idx < B) {
            // Row is 32 bytes; only x0..x2 used. 16B aligned vector load.
            float4 x = __ldg(reinterpret_cast<const float4*>(in) + idx * 2);
            float s0, c0, s1, c1, s2, c2;
            __sincosf(x.x, &s0, &c0);
            __sincosf(x.y, &s1, &c1);
            __sincosf(x.z, &s2, &c2);

            float z = 0.f;
            #pragma unroll
            for (int p0 = 0; p0 < 3; p0++) {
                float u = 0.f;
                #pragma unroll
                for (int p1 = 0; p1 < 3; p1++) {
                    const float* d = &D[p0 * 9 + p1 * 3];
                    float v = d[0] + d[1] * c2 + d[2] * s2;
                    float m1 = (p1 == 0) ? 1.f : ((p1 == 1) ? c1 : s1);
                    u = fmaf(v, m1, u);
                }
                float m0 = (p0 == 0) ? 1.f : ((p0 == 1) ? c0 : s0);
                z = fmaf(u, m0, z);
            }
            out[idx] = z;
        }
    }
}

extern "C" void kernel_launch(void* const* d_in, const int* in_sizes, int n_in,
                              void* d_out, int out_size) {
    // inputs: (B,8) float32; q_weights: (3,3,2)=18 float32.  Be robust to order.
    const float* in = (const float*)d_in[0];
    const float* w  = (const float*)d_in[1];
    int sz0 = in_sizes[0], sz1 = in_sizes[1];
    if (sz0 == 18 && sz1 != 18) {
        const float* tmp = in; in = w; w = tmp;
        int ts = sz0; sz0 = sz1; sz1 = ts;
    }
    int B = sz0 / 8;
    float* out = (float*)d_out;

    vqc_setup_kernel<<<1, 64>>>(w);
    int grid = (B + TPB * ILP - 1) / (TPB * ILP);
    vqc_main_kernel<<<grid, TPB>>>(in, out, B);
}

// round 6
// speedup vs baseline: 1.2113x; 1.1905x over previous
#include <cuda_runtime.h>
#include <cuda_bf16.h>

// ---------------------------------------------------------------------------
// QuantumLayerVQC — 3-qubit, 3-layer VQC, B ~ 1M samples.
//
// z(b) = psi(b)^T ReM psi(b), psi = kron_q (cos x_q/2, sin x_q/2),
// ReM = Re(U^dag Z0 U) depends only on q_weights. Per qubit the quadratic
// monomials {c^2, s^2, cs} map to {1, cos x, sin x} (double angle), so z is
// trilinear in m_q = (1, cos x_q, sin x_q) with 27 coefficients D.
//
// Kernel 1 (1 block, fast __sincosf): evolve 8 basis columns -> U -> ReM -> D.
// Kernel 2 (streaming, ILP=8 front-batched loads): float4 load, 3x sincos,
//          26 FMA, store. DRAM-bound; floor = 32MB in + 4MB out.
// ---------------------------------------------------------------------------

__device__ float g_D[27];

__device__ __forceinline__ void swp(float& a, float& b) { float t = a; a = b; b = t; }

__global__ void vqc_setup_kernel(const float* __restrict__ w) {
    // w: (3 layers, 3 qubits, 2) = 18 floats: [l][q][0]=RY angle, [l][q][1]=RZ angle
    __shared__ float Ur[8][8];  // [amplitude k][column j]
    __shared__ float Ui[8][8];
    __shared__ float Ms[8][8];  // ReM

    int t = threadIdx.x;

    if (t < 8) {
        // Evolve basis column j = t through the parameterized circuit.
        float ur[8], ui[8];
        #pragma unroll
        for (int k = 0; k < 8; k++) { ur[k] = (k == t) ? 1.f : 0.f; ui[k] = 0.f; }

        for (int l = 0; l < 3; l++) {
            for (int q = 0; q < 3; q++) {
                float thy = w[(l * 3 + q) * 2 + 0];
                float thz = w[(l * 3 + q) * 2 + 1];
                int s = 4 >> q;  // bit stride: q0->4, q1->2, q2->1

                // RY(thy) on qubit q: real rotation on (i, i+s) pairs.
                // Fast sincos: angles are small (weights ~N(0,0.05)); abs err
                // ~1e-7, far under the 1e-3 rel-err budget.
                float cy, sy; __sincosf(0.5f * thy, &sy, &cy);
                #pragma unroll
                for (int i = 0; i < 8; i++) {
                    if (i & s) continue;
                    float ar = ur[i],     ai = ui[i];
                    float br = ur[i + s], bi = ui[i + s];
                    ur[i]     = cy * ar - sy * br;  ui[i]     = cy * ai - sy * bi;
                    ur[i + s] = sy * ar + cy * br;  ui[i + s] = sy * ai + cy * bi;
                }

                // RZ(thz): bit=0 -> e^{-i thz/2}, bit=1 -> e^{+i thz/2}
                float cz, sz; __sincosf(0.5f * thz, &sz, &cz);
                #pragma unroll
                for (int i = 0; i < 8; i++) {
                    float ph = (i & s) ? sz : -sz;  // imaginary part of phase
                    float ar = ur[i], ai = ui[i];
                    ur[i] = cz * ar - ph * ai;
                    ui[i] = cz * ai + ph * ar;
                }
            }
            // CNOT01 (control bit2, target bit1): swap 4<->6, 5<->7
            swp(ur[4], ur[6]); swp(ui[4], ui[6]);
            swp(ur[5], ur[7]); swp(ui[5], ui[7]);
            // CNOT12 (control bit1, target bit0): swap 2<->3, 6<->7
            swp(ur[2], ur[3]); swp(ui[2], ui[3]);
            swp(ur[6], ur[7]); swp(ui[6], ui[7]);
        }
        #pragma unroll
        for (int k = 0; k < 8; k++) { Ur[k][t] = ur[k]; Ui[k][t] = ui[k]; }
    }
    __syncthreads();

    if (t < 64) {
        // ReM[i][j] = sum_k sign(k) * Re(conj(U[k][i]) * U[k][j]),
        // sign = +1 for k<4 (q0=0), -1 otherwise.
        int i = t >> 3, j = t & 7;
        float m = 0.f;
        #pragma unroll
        for (int k = 0; k < 8; k++) {
            float sgn = (k < 4) ? 1.f : -1.f;
            m += sgn * (Ur[k][i] * Ur[k][j] + Ui[k][i] * Ui[k][j]);
        }
        Ms[i][j] = m;
    }
    __syncthreads();

    if (t < 27) {
        // Per-qubit pair-(b,b') -> basis (1, cos, sin) transform:
        //   c^2 = 1/2 + 1/2 cos,  c*s = 1/2 sin,  s^2 = 1/2 - 1/2 cos
        const float T[4][3] = {
            {0.5f,  0.5f, 0.0f},   // (0,0)
            {0.0f,  0.0f, 0.5f},   // (0,1)
            {0.0f,  0.0f, 0.5f},   // (1,0)
            {0.5f, -0.5f, 0.0f},   // (1,1)
        };
        int p0 = t / 9, p1 = (t / 3) % 3, p2 = t % 3;
        float d = 0.f;
        #pragma unroll
        for (int i = 0; i < 8; i++) {
            #pragma unroll
            for (int j = 0; j < 8; j++) {
                int pr0 = (((i >> 2) & 1) << 1) | ((j >> 2) & 1);
                int pr1 = (((i >> 1) & 1) << 1) | ((j >> 1) & 1);
                int pr2 = ((i & 1) << 1) | (j & 1);
                d += Ms[i][j] * T[pr0][p0] * T[pr1][p1] * T[pr2][p2];
            }
        }
        g_D[t] = d;
    }
}

static constexpr int TPB = 256;
static constexpr int ILP = 8;

__device__ __forceinline__ float vqc_eval(const float* __restrict__ D, float4 x) {
    float s0, c0, s1, c1, s2, c2;
    __sincosf(x.x, &s0, &c0);
    __sincosf(x.y, &s1, &c1);
    __sincosf(x.z, &s2, &c2);

    float z = 0.f;
    #pragma unroll
    for (int p0 = 0; p0 < 3; p0++) {
        float u = 0.f;
        #pragma unroll
        for (int p1 = 0; p1 < 3; p1++) {
            const float* d = &D[p0 * 9 + p1 * 3];
            float v = fmaf(d[2], s2, fmaf(d[1], c2, d[0]));
            float m1 = (p1 == 0) ? 1.f : ((p1 == 1) ? c1 : s1);
            u = fmaf(v, m1, u);
        }
        float m0 = (p0 == 0) ? 1.f : ((p0 == 1) ? c0 : s0);
        z = fmaf(u, m0, z);
    }
    return z;
}

__global__ void __launch_bounds__(TPB) vqc_main_kernel(
    const float4* __restrict__ in,  // (B, 8) floats = (B, 2) float4; we use [2*i]
    float* __restrict__ out,        // (B,)
    int B
) {
    int base = blockIdx.x * (TPB * ILP) + threadIdx.x;

    if (base + (ILP - 1) * TPB < B) {
        // Fast path: front-batch ALL long-latency DRAM loads (MLP_p1 = ILP).
        float4 x[ILP];
        #pragma unroll
        for (int it = 0; it < ILP; it++)
            x[it] = __ldg(in + (base + it * TPB) * 2);

        // Warp-uniform coefficients (L2/L1-resident after first warp).
        float D[27];
        #pragma unroll
        for (int i = 0; i < 27; i++) D[i] = g_D[i];

        #pragma unroll
        for (int it = 0; it < ILP; it++)
            out[base + it * TPB] = vqc_eval(D, x[it]);
    } else {
        float D[27];
        #pragma unroll
        for (int i = 0; i < 27; i++) D[i] = g_D[i];
        #pragma unroll
        for (int it = 0; it < ILP; it++) {
            int idx = base + it * TPB;
            if (idx < B) {
                float4 x = __ldg(in + idx * 2);
                out[idx] = vqc_eval(D, x);
            }
        }
    }
}

extern "C" void kernel_launch(void* const* d_in, const int* in_sizes, int n_in,
                              void* d_out, int out_size) {
    // inputs: (B,8) float32; q_weights: (3,3,2)=18 float32.  Be robust to order.
    const float* in = (const float*)d_in[0];
    const float* w  = (const float*)d_in[1];
    int sz0 = in_sizes[0], sz1 = in_sizes[1];
    if (sz0 == 18 && sz1 != 18) {
        const float* tmp = in; in = w; w = tmp;
        int ts = sz0; sz0 = sz1; sz1 = ts;
    }
    int B = sz0 / 8;
    float* out = (float*)d_out;

    vqc_setup_kernel<<<1, 64>>>(w);
    int grid = (B + TPB * ILP - 1) / (TPB * ILP);
    vqc_main_kernel<<<grid, TPB>>>(reinterpret_cast<const float4*>(in), out, B);
}